// round 15
// baseline (speedup 1.0000x reference)
#include <cuda_runtime.h>
#include <cuda_bf16.h>

// B=2, L=256, D=256. ONE fused kernel, 128 blocks (b x 64 dg) x 1024 threads.
// Block owns 4 complex d (8 n cols), all 256 l, all 256 k.
// GEMM: 4 k-tiles of 64, double-buffered cp.async; thread = (lg 0..127, kg 0..7)
//       computes rows {lg, lg+128} x 8 n x 16 k2 with W cached in regs.
// Then k-combine in smem, epilogue, and in-block reverse complex scan.

#define XS_STRIDE 66
#define XS_TILE_BYTES (256 * XS_STRIDE * 4)    // 67584
#define WK_OFF   (2 * XS_TILE_BYTES)           // 135168
#define SA_OFF   WK_OFF                        // sA aliases Wk (8192 B)
#define XSR_OFF  (WK_OFF + 8192)               // 143360, xsr 4096 B
#define WAG_OFF  (XSR_OFF + 4096)              // 147456, 3 x 256 B
#define SMEM_DYN (WAG_OFF + 1024)              // 148480

__device__ __forceinline__ float2 cmul(float2 a, float2 b) {
    return make_float2(a.x * b.x - a.y * b.y, a.x * b.y + a.y * b.x);
}
__device__ __forceinline__ float2 cadd(float2 a, float2 b) {
    return make_float2(a.x + b.x, a.y + b.y);
}
#define FMA2(acc, x, w) \
    asm("fma.rn.f32x2 %0, %1, %2, %0;" : "+l"(acc) : "l"(x), "l"(w))
#define ADD2(acc, y) \
    asm("add.rn.f32x2 %0, %0, %1;" : "+l"(acc) : "l"(y))
#define CP_ASYNC8(dst_u32, src_ptr) \
    asm volatile("cp.async.ca.shared.global [%0], [%1], 8;" \
                 :: "r"(dst_u32), "l"(src_ptr))
#define CP_COMMIT() asm volatile("cp.async.commit_group;")
#define CP_WAIT1()  asm volatile("cp.async.wait_group 1;")
#define CP_WAIT0()  asm volatile("cp.async.wait_group 0;")

__global__ __launch_bounds__(1024, 1)
void sioconv_fused(const float* __restrict__ X, const float* __restrict__ W,
                   const float* __restrict__ h0r, const float* __restrict__ h0i,
                   float* __restrict__ out) {
    extern __shared__ __align__(16) char smem[];
    float*  Xs = (float*)smem;                   // [2][256][66]
    float2* Wk = (float2*)(smem + WK_OFF);       // [128 k2][8 n]

    const int b  = blockIdx.x >> 6;
    const int dg = blockIdx.x & 63;
    const int n0 = dg * 8;
    const int d0 = dg * 4;
    const int t  = threadIdx.x;       // 0..1023

    const float* Xb = X + b * 65536;
    const unsigned smem_base = (unsigned)__cvta_generic_to_shared(smem);

    // ---- group 0: W (1 float2/thread) + tile 0 into buf 0
    {
        int n = t & 7, k2 = t >> 3;
        CP_ASYNC8(smem_base + WK_OFF + (unsigned)(k2 * 8 + n) * 8,
                  W + (n0 + n) * 256 + 2 * k2);
    }
#pragma unroll
    for (int i = 0; i < 8; i++) {
        int e = t + 1024 * i;            // 0..8191
        int l = e >> 5, c = e & 31;      // row, k-pair within tile
        CP_ASYNC8(smem_base + (unsigned)(l * XS_STRIDE + 2 * c) * 4,
                  Xb + l * 256 + 0 * 64 + 2 * c);
    }
    CP_COMMIT();
    // ---- group 1: tile 1 into buf 1
#pragma unroll
    for (int i = 0; i < 8; i++) {
        int e = t + 1024 * i;
        int l = e >> 5, c = e & 31;
        CP_ASYNC8(smem_base + (unsigned)XS_TILE_BYTES +
                      (unsigned)(l * XS_STRIDE + 2 * c) * 4,
                  Xb + l * 256 + 1 * 64 + 2 * c);
    }
    CP_COMMIT();

    const int lg = t & 127;              // row pair: lg, lg+128
    const int kg = t >> 7;               // 0..7: k-slice (4 k2 per tile)

    unsigned long long accA[8], accB[8];
#pragma unroll
    for (int n = 0; n < 8; n++) { accA[n] = 0ull; accB[n] = 0ull; }

#pragma unroll
    for (int tile = 0; tile < 4; tile++) {
        if (tile < 2) { CP_WAIT1(); } else { CP_WAIT0(); }
        __syncthreads();

        const float*  xrA = Xs + (tile & 1) * (256 * XS_STRIDE)
                               + lg * XS_STRIDE + kg * 8;
        const float*  xrB = xrA + 128 * XS_STRIDE;
        const float2* wr  = Wk + (tile * 32 + kg * 4) * 8;
#pragma unroll
        for (int j = 0; j < 4; j++) {
            unsigned long long xA = *(const unsigned long long*)(xrA + 2 * j);
            unsigned long long xB = *(const unsigned long long*)(xrB + 2 * j);
            const ulonglong2* wp = (const ulonglong2*)(wr + j * 8);
            ulonglong2 w0 = wp[0], w1 = wp[1], w2 = wp[2], w3 = wp[3];
            FMA2(accA[0], xA, w0.x); FMA2(accA[1], xA, w0.y);
            FMA2(accA[2], xA, w1.x); FMA2(accA[3], xA, w1.y);
            FMA2(accA[4], xA, w2.x); FMA2(accA[5], xA, w2.y);
            FMA2(accA[6], xA, w3.x); FMA2(accA[7], xA, w3.y);
            FMA2(accB[0], xB, w0.x); FMA2(accB[1], xB, w0.y);
            FMA2(accB[2], xB, w1.x); FMA2(accB[3], xB, w1.y);
            FMA2(accB[4], xB, w2.x); FMA2(accB[5], xB, w2.y);
            FMA2(accB[6], xB, w3.x); FMA2(accB[7], xB, w3.y);
        }
        __syncthreads();
        if (tile < 2) {
            const int nt = tile + 2;
            unsigned dbase = smem_base + (unsigned)((tile & 1) * XS_TILE_BYTES);
#pragma unroll
            for (int i = 0; i < 8; i++) {
                int e = t + 1024 * i;
                int l = e >> 5, c = e & 31;
                CP_ASYNC8(dbase + (unsigned)(l * XS_STRIDE + 2 * c) * 4,
                          Xb + l * 256 + nt * 64 + 2 * c);
            }
            CP_COMMIT();
        }
    }
    __syncthreads();   // all Xs/Wk reads for GEMM done

    // ---- all-write k-combine scratch: u64[8 kg][256 row][8 n] (aliases Xs)
    unsigned long long* scratch = (unsigned long long*)smem;
    {
        unsigned long long* pA = scratch + ((kg * 256) + lg) * 8;
        unsigned long long* pB = scratch + ((kg * 256) + lg + 128) * 8;
#pragma unroll
        for (int n = 0; n < 8; n++) { pA[n] = accA[n]; pB[n] = accB[n]; }
    }
    __syncthreads();

    float2* sA   = (float2*)(smem + SA_OFF);    // [4][256] (aliases Wk)
    float*  xsr  = (float*)(smem + XSR_OFF);    // [4][256]
    float2* wagA = (float2*)(smem + WAG_OFF);   // [4][8]
    float2* wagY = (float2*)(smem + WAG_OFF + 256);
    float2* preY = (float2*)(smem + WAG_OFF + 512);

    // ---- reduce + epilogue: thread t owns (row2 = t&255, p = t>>8)
    {
        const int row2 = t & 255;
        const int p = t >> 8;
        unsigned long long aRe = 0ull, aIm = 0ull;
#pragma unroll
        for (int q = 0; q < 8; q++) {
            const unsigned long long* s = scratch + ((q * 256) + row2) * 8;
            ADD2(aRe, s[2 * p]);
            ADD2(aIm, s[2 * p + 1]);
        }
        float r0, r1, i0, i1;
        asm("mov.b64 {%0, %1}, %2;" : "=f"(r0), "=f"(r1) : "l"(aRe));
        asm("mov.b64 {%0, %1}, %2;" : "=f"(i0), "=f"(i1) : "l"(aIm));
        float re = r0 + r1;
        float im = i0 + i1;
        float mag2 = re * re + im * im;
        float s2 = rsqrtf(mag2) * expf(-mag2);
        sA[p * 256 + row2] = make_float2(re * s2, im * s2);
    }
    // ---- stage xhat real parts: xsr[j][l]
    {
        int l = t >> 2, jj = t & 3;
        int d = d0 + jj;
        xsr[jj * 256 + l] = (l == 0) ? h0r[d] : Xb[(l - 1) * 256 + d];
    }
    __syncthreads();

    // ---- reverse complex scan: group g = t>>8 handles series d0+g
    const int g = t >> 8;
    const int tl = t & 255;           // reversed index
    const int l = 255 - tl;
    const int lane = t & 31;
    const int w = tl >> 5;
    const int d = d0 + g;

    float2 A, Y;
    {
        float2 a = sA[g * 256 + l];
        float2 xh;
        xh.x = xsr[g * 256 + l];
        xh.y = (l == 0) ? h0i[d] : 0.f;
        A = a;
        Y = cmul(a, xh);
    }

    const unsigned mask = 0xffffffffu;
#pragma unroll
    for (int o = 1; o < 32; o <<= 1) {
        float2 pA, pY;
        pA.x = __shfl_up_sync(mask, A.x, o);
        pA.y = __shfl_up_sync(mask, A.y, o);
        pY.x = __shfl_up_sync(mask, Y.x, o);
        pY.y = __shfl_up_sync(mask, Y.y, o);
        if (lane >= o) {
            float2 nY = cadd(Y, cmul(A, pY));
            float2 nA = cmul(A, pA);
            Y = nY;
            A = nA;
        }
    }

    if (lane == 31) {
        wagA[g * 8 + w] = A;
        wagY[g * 8 + w] = Y;
    }
    __syncthreads();
    if (tl == 0) {
        float2 pY = make_float2(0.f, 0.f);
#pragma unroll
        for (int w2 = 0; w2 < 8; w2++) {
            preY[g * 8 + w2] = pY;
            pY = cadd(wagY[g * 8 + w2], cmul(wagA[g * 8 + w2], pY));
        }
    }
    __syncthreads();

    float2 Yf = Y;
    if (w > 0) Yf = cadd(Yf, cmul(A, preY[g * 8 + w]));
    float r = Yf.x;
    if (l >= 1)   r += xsr[g * 256 + (l - 1)];
    if (l == 255) r += Xb[255 * 256 + d];
    out[(b * 256 + l) * 256 + d] = r;
}

extern "C" void kernel_launch(void* const* d_in, const int* in_sizes, int n_in,
                              void* d_out, int out_size) {
    const float* x   = (const float*)d_in[0];
    const float* W   = (const float*)d_in[1];
    const float* h0r = (const float*)d_in[2];
    const float* h0i = (const float*)d_in[3];
    float* out = (float*)d_out;

    cudaFuncSetAttribute(sioconv_fused,
                         cudaFuncAttributeMaxDynamicSharedMemorySize, SMEM_DYN);
    sioconv_fused<<<128, 1024, SMEM_DYN>>>(x, W, h0r, h0i, out);
}